// round 2
// baseline (speedup 1.0000x reference)
#include <cuda_runtime.h>
#include <cstdint>

// Problem constants
#define BDIM   1024      // D
#define TSEQ   2048      // T
#define NBAT   4         // B
#define MROWS  8192      // B*T
#define NREL   129       // 2R+1
#define QRS    132       // qr row stride (padded, 16B-aligned rows)

// Scratch (allocation-free rule: __device__ globals)
__device__ float g_q [2ull * MROWS * BDIM];   // pre-scaled queries, per head
__device__ float g_k [2ull * MROWS * BDIM];   // keys, per head
__device__ float g_qr[2ull * MROWS * QRS];    // q . rel[r], per head

// ---------------------------------------------------------------------------
// Kernel 1: projection GEMM (NN).  C = scale * (A @ W + bias)
// A: [8192,1024] row-major, W: [1024,1024] row-major (W[k][n]).
// 128x128x8 tile, 256 threads, 8x8 microtile with 64-offset layout.
// ---------------------------------------------------------------------------
__global__ __launch_bounds__(256, 2)
void proj_gemm(const float* __restrict__ A, const float* __restrict__ W,
               const float* __restrict__ bias, int head, int is_k, float scale)
{
    float* C = (is_k ? g_k : g_q) + (size_t)head * MROWS * BDIM;

    __shared__ __align__(16) float As[8][128];   // [k][m]
    __shared__ __align__(16) float Ws[8][128];   // [k][n]

    const int tid = threadIdx.x;
    const int bm  = blockIdx.y * 128;
    const int bn  = blockIdx.x * 128;

    // A tile load map: 128 rows x 8 cols -> 256 float4, one per thread
    const int a_row  = tid >> 1;
    const int a_col4 = (tid & 1) * 4;
    // W tile load map: 8 rows x 128 cols -> 256 float4
    const int w_row  = tid >> 5;
    const int w_col  = (tid & 31) * 4;

    const int tx = tid & 15;   // n direction
    const int ty = tid >> 4;   // m direction

    float acc[8][8] = {};

    const float* Aptr = A + (size_t)(bm + a_row) * BDIM + a_col4;
    const float* Wptr = W + (size_t)w_row * BDIM + bn + w_col;

    for (int k0 = 0; k0 < BDIM; k0 += 8) {
        float4 av = *(const float4*)(Aptr + k0);
        float4 wv = *(const float4*)(Wptr + (size_t)k0 * BDIM);
        As[a_col4 + 0][a_row] = av.x;
        As[a_col4 + 1][a_row] = av.y;
        As[a_col4 + 2][a_row] = av.z;
        As[a_col4 + 3][a_row] = av.w;
        *(float4*)&Ws[w_row][w_col] = wv;
        __syncthreads();

        #pragma unroll
        for (int kk = 0; kk < 8; ++kk) {
            float4 a0 = *(const float4*)&As[kk][ty * 4];
            float4 a1 = *(const float4*)&As[kk][64 + ty * 4];
            float4 b0 = *(const float4*)&Ws[kk][tx * 4];
            float4 b1 = *(const float4*)&Ws[kk][64 + tx * 4];
            float ra[8] = {a0.x, a0.y, a0.z, a0.w, a1.x, a1.y, a1.z, a1.w};
            float rb[8] = {b0.x, b0.y, b0.z, b0.w, b1.x, b1.y, b1.z, b1.w};
            #pragma unroll
            for (int i = 0; i < 8; ++i)
                #pragma unroll
                for (int j = 0; j < 8; ++j)
                    acc[i][j] += ra[i] * rb[j];
        }
        __syncthreads();
    }

    // Epilogue: (acc + bias) * scale, vectorized stores
    #pragma unroll
    for (int i2 = 0; i2 < 2; ++i2)
        #pragma unroll
        for (int i = 0; i < 4; ++i) {
            const int m = bm + i2 * 64 + ty * 4 + i;
            #pragma unroll
            for (int j2 = 0; j2 < 2; ++j2) {
                const int n = bn + j2 * 64 + tx * 4;
                float4 bv = *(const float4*)&bias[n];
                float4 o;
                o.x = (acc[i2 * 4 + i][j2 * 4 + 0] + bv.x) * scale;
                o.y = (acc[i2 * 4 + i][j2 * 4 + 1] + bv.y) * scale;
                o.z = (acc[i2 * 4 + i][j2 * 4 + 2] + bv.z) * scale;
                o.w = (acc[i2 * 4 + i][j2 * 4 + 3] + bv.w) * scale;
                *(float4*)&C[(size_t)m * BDIM + n] = o;
            }
        }
}

// ---------------------------------------------------------------------------
// Kernel 2: qr = q @ rel^T  (NT, small N=129 with bounds).
// 64x64x16 tile, 256 threads, 4x4 microtile.
// ---------------------------------------------------------------------------
__global__ __launch_bounds__(256)
void qr_gemm(const float* __restrict__ rel, int head)
{
    const float* A  = g_q  + (size_t)head * MROWS * BDIM;
    float*      out = g_qr + (size_t)head * MROWS * QRS;

    __shared__ __align__(16) float As[16][64];   // [k][m]
    __shared__ __align__(16) float Bs[16][64];   // [k][n]

    const int tid = threadIdx.x;
    const int bm  = blockIdx.y * 64;
    const int bn  = blockIdx.x * 64;

    const int lrow = tid >> 2;          // 0..63
    const int lc4  = (tid & 3) * 4;     // 0,4,8,12
    const int tx   = tid & 15;
    const int ty   = tid >> 4;

    float acc[4][4] = {};

    const float* Aptr = A + (size_t)(bm + lrow) * BDIM + lc4;
    const int    nrow = bn + lrow;
    const float* Bptr = rel + (size_t)nrow * BDIM + lc4;

    for (int k0 = 0; k0 < BDIM; k0 += 16) {
        float4 av = *(const float4*)(Aptr + k0);
        float4 bv = (nrow < NREL) ? *(const float4*)(Bptr + k0)
                                  : make_float4(0.f, 0.f, 0.f, 0.f);
        As[lc4 + 0][lrow] = av.x; As[lc4 + 1][lrow] = av.y;
        As[lc4 + 2][lrow] = av.z; As[lc4 + 3][lrow] = av.w;
        Bs[lc4 + 0][lrow] = bv.x; Bs[lc4 + 1][lrow] = bv.y;
        Bs[lc4 + 2][lrow] = bv.z; Bs[lc4 + 3][lrow] = bv.w;
        __syncthreads();

        #pragma unroll
        for (int kk = 0; kk < 16; ++kk) {
            float4 a = *(const float4*)&As[kk][ty * 4];
            float4 b = *(const float4*)&Bs[kk][tx * 4];
            float ra[4] = {a.x, a.y, a.z, a.w};
            float rb[4] = {b.x, b.y, b.z, b.w};
            #pragma unroll
            for (int i = 0; i < 4; ++i)
                #pragma unroll
                for (int j = 0; j < 4; ++j)
                    acc[i][j] += ra[i] * rb[j];
        }
        __syncthreads();
    }

    #pragma unroll
    for (int i = 0; i < 4; ++i) {
        const int m = bm + ty * 4 + i;
        #pragma unroll
        for (int j = 0; j < 4; ++j) {
            const int n = bn + tx * 4 + j;
            if (n < NREL) out[(size_t)m * QRS + n] = acc[i][j];
        }
    }
}

// ---------------------------------------------------------------------------
// Kernel 3: batched scores (NT) with fused relative-position bias + mask.
// C[b,i,j] = q[b,i].k[b,j] + qr[b,i,clip(j-i,-64,64)+64], masked.
// grid.z = head*4 + batch; 128x128x8 tile.
// ---------------------------------------------------------------------------
__global__ __launch_bounds__(256, 2)
void scores_kernel(const int* __restrict__ mask, float* __restrict__ outp)
{
    const int z = blockIdx.z;            // h*4 + b
    const int h = z >> 2;
    const int b = z & 3;

    const float* A  = g_q  + ((size_t)h * MROWS + (size_t)b * TSEQ) * BDIM;
    const float* Bk = g_k  + ((size_t)h * MROWS + (size_t)b * TSEQ) * BDIM;
    const float* qr = g_qr + ((size_t)h * MROWS + (size_t)b * TSEQ) * QRS;
    const int*   mk = mask + (size_t)b * TSEQ * TSEQ;
    float*       C  = outp + (size_t)z * TSEQ * TSEQ;

    __shared__ __align__(16) float As[8][128];   // [k][i]
    __shared__ __align__(16) float Bs[8][128];   // [k][j]

    const int tid = threadIdx.x;
    const int bm  = blockIdx.y * 128;    // i tile
    const int bn  = blockIdx.x * 128;    // j tile

    const int l_row  = tid >> 1;
    const int l_col4 = (tid & 1) * 4;
    const int tx = tid & 15;
    const int ty = tid >> 4;

    float acc[8][8] = {};

    const float* Aptr = A  + (size_t)(bm + l_row) * BDIM + l_col4;
    const float* Bptr = Bk + (size_t)(bn + l_row) * BDIM + l_col4;

    for (int k0 = 0; k0 < BDIM; k0 += 8) {
        float4 av = *(const float4*)(Aptr + k0);
        float4 bv = *(const float4*)(Bptr + k0);
        As[l_col4 + 0][l_row] = av.x; As[l_col4 + 1][l_row] = av.y;
        As[l_col4 + 2][l_row] = av.z; As[l_col4 + 3][l_row] = av.w;
        Bs[l_col4 + 0][l_row] = bv.x; Bs[l_col4 + 1][l_row] = bv.y;
        Bs[l_col4 + 2][l_row] = bv.z; Bs[l_col4 + 3][l_row] = bv.w;
        __syncthreads();

        #pragma unroll
        for (int kk = 0; kk < 8; ++kk) {
            float4 a0 = *(const float4*)&As[kk][ty * 4];
            float4 a1 = *(const float4*)&As[kk][64 + ty * 4];
            float4 b0 = *(const float4*)&Bs[kk][tx * 4];
            float4 b1 = *(const float4*)&Bs[kk][64 + tx * 4];
            float ra[8] = {a0.x, a0.y, a0.z, a0.w, a1.x, a1.y, a1.z, a1.w};
            float rb[8] = {b0.x, b0.y, b0.z, b0.w, b1.x, b1.y, b1.z, b1.w};
            #pragma unroll
            for (int i = 0; i < 8; ++i)
                #pragma unroll
                for (int j = 0; j < 8; ++j)
                    acc[i][j] += ra[i] * rb[j];
        }
        __syncthreads();
    }

    // Epilogue: + qr[i, clip(j-i)+64], mask select, vectorized store
    #pragma unroll
    for (int i2 = 0; i2 < 2; ++i2)
        #pragma unroll
        for (int i = 0; i < 4; ++i) {
            const int iRow = bm + i2 * 64 + ty * 4 + i;
            const float* qrow = qr + (size_t)iRow * QRS;
            #pragma unroll
            for (int j2 = 0; j2 < 2; ++j2) {
                const int jBase = bn + j2 * 64 + tx * 4;
                int4 mv = *(const int4*)&mk[(size_t)iRow * TSEQ + jBase];
                float4 o;
                {
                    int d0 = jBase + 0 - iRow; d0 = min(max(d0, -64), 64) + 64;
                    int d1 = jBase + 1 - iRow; d1 = min(max(d1, -64), 64) + 64;
                    int d2 = jBase + 2 - iRow; d2 = min(max(d2, -64), 64) + 64;
                    int d3 = jBase + 3 - iRow; d3 = min(max(d3, -64), 64) + 64;
                    float v0 = acc[i2 * 4 + i][j2 * 4 + 0] + qrow[d0];
                    float v1 = acc[i2 * 4 + i][j2 * 4 + 1] + qrow[d1];
                    float v2 = acc[i2 * 4 + i][j2 * 4 + 2] + qrow[d2];
                    float v3 = acc[i2 * 4 + i][j2 * 4 + 3] + qrow[d3];
                    o.x = mv.x ? v0 : -1e18f;
                    o.y = mv.y ? v1 : -1e18f;
                    o.z = mv.z ? v2 : -1e18f;
                    o.w = mv.w ? v3 : -1e18f;
                }
                *(float4*)&C[(size_t)iRow * TSEQ + jBase] = o;
            }
        }
}

// ---------------------------------------------------------------------------
extern "C" void kernel_launch(void* const* d_in, const int* in_sizes, int n_in,
                              void* d_out, int out_size)
{
    const float* repre  = (const float*)d_in[0];
    const int*   mask   = (const int*)  d_in[1];
    const float* st_Wq  = (const float*)d_in[2];
    const float* st_bq  = (const float*)d_in[3];
    const float* st_Wk  = (const float*)d_in[4];
    const float* st_bk  = (const float*)d_in[5];
    const float* st_rel = (const float*)d_in[6];
    const float* ed_Wq  = (const float*)d_in[7];
    const float* ed_bq  = (const float*)d_in[8];
    const float* ed_Wk  = (const float*)d_in[9];
    const float* ed_bk  = (const float*)d_in[10];
    const float* ed_rel = (const float*)d_in[11];
    float* out = (float*)d_out;

    const float qscale = 1.0f / 32.0f;   // 1/sqrt(1024)

    dim3 pgrid(BDIM / 128, MROWS / 128);          // (8, 64)
    proj_gemm<<<pgrid, 256>>>(repre, st_Wq, st_bq, 0, 0, qscale);
    proj_gemm<<<pgrid, 256>>>(repre, st_Wk, st_bk, 0, 1, 1.0f);
    proj_gemm<<<pgrid, 256>>>(repre, ed_Wq, ed_bq, 1, 0, qscale);
    proj_gemm<<<pgrid, 256>>>(repre, ed_Wk, ed_bk, 1, 1, 1.0f);

    dim3 qgrid(3, MROWS / 64);                    // covers N=129
    qr_gemm<<<qgrid, 256>>>(st_rel, 0);
    qr_gemm<<<qgrid, 256>>>(ed_rel, 1);

    dim3 sgrid(TSEQ / 128, TSEQ / 128, 8);        // (16,16, head*4+batch)
    scores_kernel<<<sgrid, 256>>>(mask, out);
}

// round 5
// speedup vs baseline: 2.6912x; 2.6912x over previous
#include <cuda_runtime.h>
#include <cuda_bf16.h>
#include <cstdint>

#define BDIM    1024
#define TSEQ    2048
#define MROWS   8192
#define NRELS   256        // padded rel rows (129 -> 256, zero-filled)
#define KCHUNKS 16         // 1024 / 64

// ---------------------------------------------------------------------------
// Scratch (__device__ globals; no allocations allowed)
// ---------------------------------------------------------------------------
__device__ __nv_bfloat16 g_rhi[(size_t)MROWS * BDIM];
__device__ __nv_bfloat16 g_rlo[(size_t)MROWS * BDIM];
__device__ __nv_bfloat16 g_qhi[2ull * MROWS * BDIM];
__device__ __nv_bfloat16 g_qlo[2ull * MROWS * BDIM];
__device__ __nv_bfloat16 g_khi[2ull * MROWS * BDIM];
__device__ __nv_bfloat16 g_klo[2ull * MROWS * BDIM];
__device__ __nv_bfloat16 g_wth[4ull * BDIM * BDIM];
__device__ __nv_bfloat16 g_wtl[4ull * BDIM * BDIM];
__device__ __nv_bfloat16 g_relh[2ull * NRELS * BDIM];
__device__ __nv_bfloat16 g_rell[2ull * NRELS * BDIM];
__device__ float         g_qr  [2ull * MROWS * NRELS];

// ---------------------------------------------------------------------------
// Helpers (baseline PTX only: cp.async / ldmatrix / mma.sync — no tcgen05)
// ---------------------------------------------------------------------------
__device__ __forceinline__ uint32_t smem_u32(const void* p) {
    uint32_t a;
    asm("{ .reg .u64 t; cvta.to.shared.u64 t, %1; cvt.u32.u64 %0, t; }"
        : "=r"(a) : "l"(p));
    return a;
}

__device__ __forceinline__ void cp_async16(uint32_t dst, const void* src) {
    asm volatile("cp.async.cg.shared.global [%0], [%1], 16;\n" :: "r"(dst), "l"(src));
}
#define CP_COMMIT() asm volatile("cp.async.commit_group;\n" ::: "memory")
#define CP_WAIT1()  asm volatile("cp.async.wait_group 1;\n" ::: "memory")
#define CP_WAIT0()  asm volatile("cp.async.wait_group 0;\n" ::: "memory")

__device__ __forceinline__ void ldsm4(uint32_t addr, uint32_t* r) {
    asm volatile("ldmatrix.sync.aligned.m8n8.x4.shared.b16 {%0,%1,%2,%3}, [%4];"
        : "=r"(r[0]), "=r"(r[1]), "=r"(r[2]), "=r"(r[3]) : "r"(addr));
}

__device__ __forceinline__ void mma_bf16(float* c, const uint32_t* a,
                                         uint32_t b0, uint32_t b1) {
    asm volatile(
        "mma.sync.aligned.m16n8k16.row.col.f32.bf16.bf16.f32 "
        "{%0,%1,%2,%3}, {%4,%5,%6,%7}, {%8,%9}, {%0,%1,%2,%3};"
        : "+f"(c[0]), "+f"(c[1]), "+f"(c[2]), "+f"(c[3])
        : "r"(a[0]), "r"(a[1]), "r"(a[2]), "r"(a[3]), "r"(b0), "r"(b1));
}

__device__ __forceinline__ void split2(float v, __nv_bfloat16& h, __nv_bfloat16& l) {
    h = __float2bfloat16(v);
    l = __float2bfloat16(v - __bfloat162float(h));
}

// ---------------------------------------------------------------------------
// Conversion kernels
// ---------------------------------------------------------------------------
__global__ void split_repre(const float* __restrict__ in) {
    const int n4 = MROWS * BDIM / 4;
    for (int i = blockIdx.x * blockDim.x + threadIdx.x; i < n4;
         i += gridDim.x * blockDim.x) {
        float4 v = reinterpret_cast<const float4*>(in)[i];
        __nv_bfloat16 h0, h1, h2, h3, l0, l1, l2, l3;
        split2(v.x, h0, l0); split2(v.y, h1, l1);
        split2(v.z, h2, l2); split2(v.w, h3, l3);
        reinterpret_cast<__nv_bfloat162*>(g_rhi)[i * 2 + 0] = __halves2bfloat162(h0, h1);
        reinterpret_cast<__nv_bfloat162*>(g_rhi)[i * 2 + 1] = __halves2bfloat162(h2, h3);
        reinterpret_cast<__nv_bfloat162*>(g_rlo)[i * 2 + 0] = __halves2bfloat162(l0, l1);
        reinterpret_cast<__nv_bfloat162*>(g_rlo)[i * 2 + 1] = __halves2bfloat162(l2, l3);
    }
}

__global__ void relpad_kernel(const float* __restrict__ rel, int head) {
    const int idx = blockIdx.x * 256 + threadIdx.x;   // [0, 256*1024)
    const int r = idx >> 10, c = idx & 1023;
    float v = (r < 129) ? rel[r * BDIM + c] : 0.0f;
    __nv_bfloat16 h, l; split2(v, h, l);
    g_relh[(size_t)head * NRELS * BDIM + idx] = h;
    g_rell[(size_t)head * NRELS * BDIM + idx] = l;
}

// W [k][n] -> Wt [n][k], split to hi/lo.  block(32,8), grid(32,32)
__global__ void transpose_split(const float* __restrict__ W, int widx) {
    __shared__ float t[32][33];
    const int n0 = blockIdx.x * 32, k0 = blockIdx.y * 32;
    for (int i = threadIdx.y; i < 32; i += 8)
        t[i][threadIdx.x] = W[(size_t)(k0 + i) * BDIM + n0 + threadIdx.x];
    __syncthreads();
    __nv_bfloat16* th = g_wth + (size_t)widx * BDIM * BDIM;
    __nv_bfloat16* tl = g_wtl + (size_t)widx * BDIM * BDIM;
    for (int i = threadIdx.y; i < 32; i += 8) {
        float v = t[threadIdx.x][i];             // = W[k0+i? no: W[k0+tx][n0+i]
        __nv_bfloat16 h, l; split2(v, h, l);
        th[(size_t)(n0 + i) * BDIM + k0 + threadIdx.x] = h;
        tl[(size_t)(n0 + i) * BDIM + k0 + threadIdx.x] = l;
    }
}

// ---------------------------------------------------------------------------
// Unified split-bf16 HMMA GEMM (NT): C[128 x 128] = A[128,1024] . B[128,1024]^T
// Stage layout (64KB): Ah@0  Al@16K  Bh@32K  Bl@48K ; each [128 rows][64 bf16]
// SW128 swizzle: off ^ ((off>>3)&0x70)  ->  16B chunk c goes to c^(r&7).
// MODE 0: proj   MODE 1: qr   MODE 2: scores
// ---------------------------------------------------------------------------
#define STAGE_BYTES 65536

__device__ __forceinline__ void load_stage(
    const __nv_bfloat16* Ah, const __nv_bfloat16* Al,
    const __nv_bfloat16* Bh, const __nv_bfloat16* Bl,
    size_t kelem, uint32_t base, int tid)
{
    const __nv_bfloat16* srcs[4] = {Ah + kelem, Al + kelem, Bh + kelem, Bl + kelem};
    #pragma unroll
    for (int m = 0; m < 4; ++m) {
        const char* s = (const char*)srcs[m];
        const uint32_t b = base + m * 16384;
        #pragma unroll
        for (int it = 0; it < 4; ++it) {
            const int t = tid + it * 256;
            const int r = t >> 3, c = t & 7;
            const uint32_t off = (uint32_t)(r * 128 + c * 16);
            cp_async16(b + (off ^ ((off >> 3) & 0x70)),
                       s + (size_t)r * (BDIM * 2) + c * 16);
        }
    }
}

template<int MODE>
__global__ __launch_bounds__(256, 1)
void gemm_kernel(int widx, const float* __restrict__ bias, float scale, int is_k,
                 int head, const int* __restrict__ maskp, float* __restrict__ outF)
{
    extern __shared__ __align__(1024) char smem[];
    const uint32_t sb = smem_u32(smem);
    const int tid  = threadIdx.x;
    const int wid  = tid >> 5;
    const int lane = tid & 31;
    const int warp_m = wid >> 2;       // 0..1  (64 rows each)
    const int warp_n = wid & 3;        // 0..3  (32 cols each)

    // Operand tile origins (k = 0)
    const __nv_bfloat16 *Ah, *Al, *Bh, *Bl;
    int hh = 0, bat = 0;
    if (MODE == 0) {
        const size_t ab = (size_t)blockIdx.y * 128 * BDIM;
        Ah = g_rhi + ab;  Al = g_rlo + ab;
        const size_t bb = (size_t)widx * BDIM * BDIM + (size_t)blockIdx.x * 128 * BDIM;
        Bh = g_wth + bb;  Bl = g_wtl + bb;
    } else if (MODE == 1) {
        const size_t ab = ((size_t)head * MROWS + (size_t)blockIdx.y * 128) * BDIM;
        Ah = g_qhi + ab;  Al = g_qlo + ab;
        const size_t bb = ((size_t)head * NRELS + (size_t)blockIdx.x * 128) * BDIM;
        Bh = g_relh + bb; Bl = g_rell + bb;
    } else {
        const int z = blockIdx.z; hh = z >> 2; bat = z & 3;
        const size_t ab = ((size_t)hh * MROWS + (size_t)bat * TSEQ
                           + (size_t)blockIdx.y * 128) * BDIM;
        const size_t bb = ((size_t)hh * MROWS + (size_t)bat * TSEQ
                           + (size_t)blockIdx.x * 128) * BDIM;
        Ah = g_qhi + ab; Al = g_qlo + ab;
        Bh = g_khi + bb; Bl = g_klo + bb;
    }

    // Per-lane ldmatrix row offsets (bytes) and k-xor
    const uint32_t xorv = (uint32_t)(lane & 7) << 4;
    uint32_t arow[4], brow[2];
    #pragma unroll
    for (int mi = 0; mi < 4; ++mi)
        arow[mi] = (uint32_t)(warp_m * 64 + mi * 16 + (lane & 15)) * 128;
    #pragma unroll
    for (int nj = 0; nj < 2; ++nj)
        brow[nj] = (uint32_t)(warp_n * 32 + nj * 16 + (lane & 7)
                              + ((lane & 16) ? 8 : 0)) * 128;
    const uint32_t ka_h = (uint32_t)((lane >> 4) * 16);        // A k-half byte
    const uint32_t kb_h = (uint32_t)(((lane >> 3) & 1) * 16);  // B k-half byte

    float acc[4][4][4] = {};

    // 3-stage pipeline
    load_stage(Ah, Al, Bh, Bl, 0,  sb,               tid); CP_COMMIT();
    load_stage(Ah, Al, Bh, Bl, 64, sb + STAGE_BYTES, tid); CP_COMMIT();

    for (int c = 0; c < KCHUNKS; ++c) {
        const uint32_t base = sb + (uint32_t)(c % 3) * STAGE_BYTES;
        CP_WAIT1();
        __syncthreads();

        #pragma unroll
        for (int ks = 0; ks < 4; ++ks) {
            const uint32_t ka = (uint32_t)(ks * 32) + ka_h;
            const uint32_t kb = (uint32_t)(ks * 32) + kb_h;
            uint32_t ah[4][4], bb_[2][4];
            #pragma unroll
            for (int mi = 0; mi < 4; ++mi)
                ldsm4(base + arow[mi] + (ka ^ xorv), ah[mi]);
            #pragma unroll
            for (int nj = 0; nj < 2; ++nj)
                ldsm4(base + 32768 + brow[nj] + (kb ^ xorv), bb_[nj]);
            #pragma unroll
            for (int mi = 0; mi < 4; ++mi)
                #pragma unroll
                for (int ni = 0; ni < 4; ++ni)
                    mma_bf16(acc[mi][ni], ah[mi],
                             bb_[ni >> 1][(ni & 1) * 2], bb_[ni >> 1][(ni & 1) * 2 + 1]);
            // Ah . Bl
            uint32_t bl[2][4];
            #pragma unroll
            for (int nj = 0; nj < 2; ++nj)
                ldsm4(base + 49152 + brow[nj] + (kb ^ xorv), bl[nj]);
            #pragma unroll
            for (int mi = 0; mi < 4; ++mi)
                #pragma unroll
                for (int ni = 0; ni < 4; ++ni)
                    mma_bf16(acc[mi][ni], ah[mi],
                             bl[ni >> 1][(ni & 1) * 2], bl[ni >> 1][(ni & 1) * 2 + 1]);
            // Al . Bh
            uint32_t al[4][4];
            #pragma unroll
            for (int mi = 0; mi < 4; ++mi)
                ldsm4(base + 16384 + arow[mi] + (ka ^ xorv), al[mi]);
            #pragma unroll
            for (int mi = 0; mi < 4; ++mi)
                #pragma unroll
                for (int ni = 0; ni < 4; ++ni)
                    mma_bf16(acc[mi][ni], al[mi],
                             bb_[ni >> 1][(ni & 1) * 2], bb_[ni >> 1][(ni & 1) * 2 + 1]);
        }
        __syncthreads();
        if (c + 2 < KCHUNKS) {
            load_stage(Ah, Al, Bh, Bl, (size_t)(c + 2) * 64,
                       sb + (uint32_t)((c + 2) % 3) * STAGE_BYTES, tid);
            CP_COMMIT();
        }
    }
    CP_WAIT0();

    // ---------------- Epilogues ----------------
    const int lr = lane >> 2;            // 0..7 row within 8-row group
    const int lc = (lane & 3) * 2;       // 0,2,4,6 col pair base

    if (MODE == 0) {
        __nv_bfloat16* outH = (is_k ? g_khi : g_qhi) + (size_t)head * MROWS * BDIM;
        __nv_bfloat16* outL = (is_k ? g_klo : g_qlo) + (size_t)head * MROWS * BDIM;
        const int gm0 = blockIdx.y * 128 + warp_m * 64;
        const int gn0 = blockIdx.x * 128 + warp_n * 32;
        #pragma unroll
        for (int mi = 0; mi < 4; ++mi)
            #pragma unroll
            for (int h = 0; h < 2; ++h) {
                const size_t rofs = (size_t)(gm0 + mi * 16 + lr + h * 8) * BDIM;
                #pragma unroll
                for (int ni = 0; ni < 4; ++ni) {
                    const int col = gn0 + ni * 8 + lc;
                    float2 bv = *reinterpret_cast<const float2*>(&bias[col]);
                    float v0 = (acc[mi][ni][h * 2 + 0] + bv.x) * scale;
                    float v1 = (acc[mi][ni][h * 2 + 1] + bv.y) * scale;
                    __nv_bfloat16 h0, h1, l0, l1;
                    split2(v0, h0, l0); split2(v1, h1, l1);
                    *reinterpret_cast<__nv_bfloat162*>(outH + rofs + col)
                        = __halves2bfloat162(h0, h1);
                    *reinterpret_cast<__nv_bfloat162*>(outL + rofs + col)
                        = __halves2bfloat162(l0, l1);
                }
            }
    } else if (MODE == 1) {
        const int gm0 = blockIdx.y * 128 + warp_m * 64;
        const int gn0 = blockIdx.x * 128 + warp_n * 32;
        float* outq = g_qr + (size_t)head * MROWS * NRELS;
        #pragma unroll
        for (int mi = 0; mi < 4; ++mi)
            #pragma unroll
            for (int h = 0; h < 2; ++h) {
                const size_t rofs = (size_t)(gm0 + mi * 16 + lr + h * 8) * NRELS;
                #pragma unroll
                for (int ni = 0; ni < 4; ++ni) {
                    const int col = gn0 + ni * 8 + lc;
                    *reinterpret_cast<float2*>(outq + rofs + col)
                        = make_float2(acc[mi][ni][h * 2], acc[mi][ni][h * 2 + 1]);
                }
            }
    } else {
        // Stage qr[128 rows][136] into smem with stride 137 (conflict-spread)
        __syncthreads();
        float* qrs = reinterpret_cast<float*>(smem);
        const float* qrg = g_qr + ((size_t)hh * MROWS + (size_t)bat * TSEQ
                                   + (size_t)blockIdx.y * 128) * NRELS;
        for (int idx = tid; idx < 128 * 34; idx += 256) {
            const int r = idx / 34, c4 = (idx % 34) * 4;
            float4 v = *reinterpret_cast<const float4*>(qrg + (size_t)r * NRELS + c4);
            float* d = qrs + r * 137 + c4;
            d[0] = v.x; d[1] = v.y; d[2] = v.z; d[3] = v.w;
        }
        __syncthreads();

        const int gn0 = blockIdx.x * 128 + warp_n * 32;
        #pragma unroll
        for (int mi = 0; mi < 4; ++mi)
            #pragma unroll
            for (int h = 0; h < 2; ++h) {
                const int rloc = warp_m * 64 + mi * 16 + lr + h * 8;   // 0..127
                const int row  = blockIdx.y * 128 + rloc;              // in batch
                const int*  mrow = maskp + ((size_t)bat * TSEQ + row) * TSEQ;
                float*      crow = outF + ((size_t)(hh * 4 + bat) * TSEQ + row) * TSEQ;
                const float* qrow = qrs + rloc * 137;
                #pragma unroll
                for (int ni = 0; ni < 4; ++ni) {
                    const int col = gn0 + ni * 8 + lc;
                    int2 mv = *reinterpret_cast<const int2*>(mrow + col);
                    int d0 = min(max(col + 0 - row, -64), 64) + 64;
                    int d1 = min(max(col + 1 - row, -64), 64) + 64;
                    float2 o;
                    o.x = mv.x ? (acc[mi][ni][h * 2 + 0] + qrow[d0]) : -1e18f;
                    o.y = mv.y ? (acc[mi][ni][h * 2 + 1] + qrow[d1]) : -1e18f;
                    *reinterpret_cast<float2*>(crow + col) = o;
                }
            }
    }
}

// ---------------------------------------------------------------------------
extern "C" void kernel_launch(void* const* d_in, const int* in_sizes, int n_in,
                              void* d_out, int out_size)
{
    const float* repre  = (const float*)d_in[0];
    const int*   mask   = (const int*)  d_in[1];
    const float* st_Wq  = (const float*)d_in[2];
    const float* st_bq  = (const float*)d_in[3];
    const float* st_Wk  = (const float*)d_in[4];
    const float* st_bk  = (const float*)d_in[5];
    const float* st_rel = (const float*)d_in[6];
    const float* ed_Wq  = (const float*)d_in[7];
    const float* ed_bq  = (const float*)d_in[8];
    const float* ed_Wk  = (const float*)d_in[9];
    const float* ed_bk  = (const float*)d_in[10];
    const float* ed_rel = (const float*)d_in[11];
    float* out = (float*)d_out;

    constexpr int SMEM = 3 * STAGE_BYTES;   // 196608
    cudaFuncSetAttribute(gemm_kernel<0>, cudaFuncAttributeMaxDynamicSharedMemorySize, SMEM);
    cudaFuncSetAttribute(gemm_kernel<1>, cudaFuncAttributeMaxDynamicSharedMemorySize, SMEM);
    cudaFuncSetAttribute(gemm_kernel<2>, cudaFuncAttributeMaxDynamicSharedMemorySize, SMEM);

    const float qscale = 1.0f / 32.0f;

    split_repre<<<2048, 256>>>(repre);
    relpad_kernel<<<NRELS * BDIM / 256, 256>>>(st_rel, 0);
    relpad_kernel<<<NRELS * BDIM / 256, 256>>>(ed_rel, 1);

    dim3 tb(32, 8), tg(32, 32);
    transpose_split<<<tg, tb>>>(st_Wq, 0);
    transpose_split<<<tg, tb>>>(st_Wk, 1);
    transpose_split<<<tg, tb>>>(ed_Wq, 2);
    transpose_split<<<tg, tb>>>(ed_Wk, 3);

    dim3 pgrid(8, 64);
    gemm_kernel<0><<<pgrid, 256, SMEM>>>(0, st_bq, qscale, 0, 0, nullptr, nullptr);
    gemm_kernel<0><<<pgrid, 256, SMEM>>>(1, st_bk, 1.0f,   1, 0, nullptr, nullptr);
    gemm_kernel<0><<<pgrid, 256, SMEM>>>(2, ed_bq, qscale, 0, 1, nullptr, nullptr);
    gemm_kernel<0><<<pgrid, 256, SMEM>>>(3, ed_bk, 1.0f,   1, 1, nullptr, nullptr);

    dim3 qgrid(2, 64);
    gemm_kernel<1><<<qgrid, 256, SMEM>>>(0, nullptr, 0.f, 0, 0, nullptr, nullptr);
    gemm_kernel<1><<<qgrid, 256, SMEM>>>(0, nullptr, 0.f, 0, 1, nullptr, nullptr);

    dim3 sgrid(16, 16, 8);
    gemm_kernel<2><<<sgrid, 256, SMEM>>>(0, nullptr, 0.f, 0, 0, mask, out);
}